// round 13
// baseline (speedup 1.0000x reference)
#include <cuda_runtime.h>
#include <cstdint>

#define B_N   65536
#define IN_N  512
#define H_N   1024
#define STEPS 10
#define BETA  0.9f
#define THR   1.0f

#define NSTRIPE 16                     // 1024 cols / 64
#define CHUNKB  32                     // b's per task (32 warps x 1)
#define NCHUNK  (B_N / CHUNKB)         // 2048
#define NTASK   (NSTRIPE * NCHUNK)     // 32768
#define LISTW   648                    // 512 entries + <=93 pad + margin
#define MAXG    36                     // <=31 groups + prefetch margin

// smem layout for k3g
#define SM_W2    0                     // 512 rows x 256B = 131072
#define SM_DUMMY 131072                // 512B zero row (offset 131072 = dummy)
#define SMEMB    (131072 + 512)

#define ADD2(d, a, b) asm("add.rn.f32x2 %0, %1, %2;" : "=l"(d) : "l"(a), "l"(b))

// ---------------- static scratch ----------------
__device__ unsigned short g_code[B_N][H_N];                // layer-1 10-bit spike codes
__device__ unsigned       g_klist[B_N][2][2][LISTW];       // [b][thalf][khalf] offsets klocal*256
__device__ unsigned       g_gdesc[B_N][2][2][MAXG];        // compact: mask5 | end<<5
__device__ unsigned short g_gcnt[B_N][2][2];               // compact group counts
__device__ unsigned short g_s2code[B_N][H_N];              // layer-2 10-bit spike codes
__device__ unsigned       g_ticket;

// ---------------- K1: cur1 GEMM + fused layer-1 LIF -> 10-bit codes ----------------
__global__ __launch_bounds__(256) void k1_gemm(const float* __restrict__ X,
                                               const float* __restrict__ W1,
                                               const float* __restrict__ b1) {
    __shared__ float As[16][128];
    __shared__ float Bs[16][128];
    const int tid = threadIdx.x;
    const int tx = tid & 15, ty = tid >> 4;
    const int m0 = blockIdx.y * 128;
    const int n0 = blockIdx.x * 128;

    float acc[8][8];
#pragma unroll
    for (int i = 0; i < 8; i++)
#pragma unroll
        for (int j = 0; j < 8; j++) acc[i][j] = 0.f;

    for (int kc = 0; kc < IN_N; kc += 16) {
        float4 av[2], bv[2];
#pragma unroll
        for (int l = 0; l < 2; l++) {
            int f = tid + l * 256;
            int row = f >> 2, kq = (f & 3) * 4;
            av[l] = *(const float4*)&X[(size_t)(m0 + row) * IN_N + kc + kq];
            int kr = f >> 5, c4 = (f & 31) * 4;
            bv[l] = *(const float4*)&W1[(size_t)(kc + kr) * H_N + n0 + c4];
        }
        __syncthreads();
#pragma unroll
        for (int l = 0; l < 2; l++) {
            int f = tid + l * 256;
            int row = f >> 2, kq = (f & 3) * 4;
            As[kq + 0][row] = av[l].x; As[kq + 1][row] = av[l].y;
            As[kq + 2][row] = av[l].z; As[kq + 3][row] = av[l].w;
            int kr = f >> 5, c4 = (f & 31) * 4;
            *(float4*)&Bs[kr][c4] = bv[l];
        }
        __syncthreads();
#pragma unroll
        for (int kk = 0; kk < 16; kk++) {
            float a[8], bb[8];
            *(float4*)&a[0]  = *(float4*)&As[kk][ty * 8];
            *(float4*)&a[4]  = *(float4*)&As[kk][ty * 8 + 4];
            *(float4*)&bb[0] = *(float4*)&Bs[kk][tx * 8];
            *(float4*)&bb[4] = *(float4*)&Bs[kk][tx * 8 + 4];
#pragma unroll
            for (int i = 0; i < 8; i++)
#pragma unroll
                for (int j = 0; j < 8; j++) acc[i][j] += a[i] * bb[j];
        }
    }

    float bias[8];
#pragma unroll
    for (int j = 0; j < 8; j++) bias[j] = b1[n0 + tx * 8 + j];

#pragma unroll
    for (int i = 0; i < 8; i++) {
        int row = m0 + ty * 8 + i;
        unsigned short codes[8];
#pragma unroll
        for (int j = 0; j < 8; j++) {
            float c = acc[i][j] + bias[j];
            float m = 0.f;
            unsigned code = 0;
#pragma unroll
            for (int t = 0; t < STEPS; t++) {
                float r = (m > THR) ? THR : 0.f;
                m = BETA * m + c - r;
                code |= (m > THR) ? (1u << t) : 0u;
            }
            codes[j] = (unsigned short)code;
        }
        *(uint4*)&g_code[row][n0 + tx * 8] = *(const uint4*)codes;
    }
}

// ---------------- K2b: per-(b, thalf, khalf) counting sort into 31 bins -------------
// warp per b. Bin = 5-bit half-code (bin 0 excluded). Groups 4-aligned; compact
// descs: mask5 | end<<5. Entries are byte offsets klocal*256 (klocal in khalf).
__global__ __launch_bounds__(256) void k2b_sort() {
    __shared__ unsigned scnt[8][32];
    const int wid  = threadIdx.x >> 5;
    const int lane = threadIdx.x & 31;
    const int b    = blockIdx.x * 8 + wid;
    const unsigned short* codes = g_code[b];
    const unsigned ltmask = (1u << lane) - 1u;
    const unsigned DUMMY = 131072u;
    if (blockIdx.x == 0 && threadIdx.x == 0) g_ticket = 0;

    for (int th = 0; th < 2; th++) {
        for (int kh = 0; kh < 2; kh++) {
            unsigned* cnt = scnt[wid];
            cnt[lane] = 0;
            __syncwarp();
            // pass 1: counts (deterministic leader-writes)
            for (int it = 0; it < 16; it++) {
                unsigned c = codes[kh * 512 + it * 32 + lane];
                unsigned g = (c >> (5 * th)) & 31u;
                unsigned mm = __match_any_sync(0xFFFFFFFFu, g);
                if (g != 0 && (__ffs(mm) - 1) == lane) cnt[g] += __popc(mm);
                __syncwarp();
            }
            unsigned cg  = (lane > 0) ? cnt[lane] : 0u;
            unsigned pad = (cg + 3u) & ~3u;
            unsigned s = pad;
#pragma unroll
            for (int off = 1; off < 32; off <<= 1) {
                unsigned n = __shfl_up_sync(0xFFFFFFFFu, s, off);
                if (lane >= off) s += n;
            }
            // compact descs in ascending mask order
            unsigned pb = __ballot_sync(0xFFFFFFFFu, (lane > 0) && (cg > 0));
            if ((lane > 0) && (cg > 0)) {
                int cidx = __popc(pb & ltmask);
                g_gdesc[b][th][kh][cidx] = (unsigned)lane | (s << 5);
            }
            if (lane == 0) g_gcnt[b][th][kh] = (unsigned short)__popc(pb);
            cnt[lane] = s - pad;                   // start cursor (4-aligned)
            __syncwarp();
            // pass 2: deterministic scatter
            for (int it = 0; it < 16; it++) {
                unsigned c = codes[kh * 512 + it * 32 + lane];
                unsigned g = (c >> (5 * th)) & 31u;
                unsigned mm = __match_any_sync(0xFFFFFFFFu, g);
                unsigned rank = __popc(mm & ltmask);
                unsigned pos0 = cnt[g];
                __syncwarp();
                if (g != 0) g_klist[b][th][kh][pos0 + rank] = (unsigned)(it * 32 + lane) * 256u;
                if (g != 0 && (__ffs(mm) - 1) == lane) cnt[g] = pos0 + __popc(mm);
                __syncwarp();
            }
            // pad each group's tail to multiple of 4 with dummies
            if (lane >= 1) {
                unsigned cur = cnt[lane], end = (cur + 3u) & ~3u;
                for (unsigned p = cur; p < end; p++) g_klist[b][th][kh][p] = DUMMY;
            }
            __syncwarp();
        }
    }
}

// ---------------- K3g: desc-driven half-code group-sum GEMM + fused layer-2 LIF ------
// Persistent CTAs (1024 thr = 32 warps). Warp owns ONE b, lane covers 2 cols (f32x2).
// W2 staged per k-half; per phase walks both temporal-half sublists (<=31 fat groups
// each); group sum scatters into 5 step-sums via its 5-bit mask.
__global__ __launch_bounds__(1024, 1) void k3g(const float* __restrict__ W2,
                                               const float* __restrict__ b2) {
    extern __shared__ char smem[];
    __shared__ unsigned sTask;
    const int tid  = threadIdx.x;
    const int lane = tid & 31, wid = tid >> 5;
    unsigned sbase;
    asm("{ .reg .u64 t; cvta.to.shared.u64 t, %1; cvt.u32.u64 %0, t; }"
        : "=r"(sbase) : "l"(smem));
    const unsigned lbase = sbase + lane * 8;      // + entry offset = lds address

    if (tid < 64) *(unsigned long long*)(smem + SM_DUMMY + tid * 8) = 0ull;
    __syncthreads();

    for (;;) {
        if (tid == 0) sTask = atomicAdd(&g_ticket, 1u);
        __syncthreads();
        const unsigned task = sTask;
        __syncthreads();
        if (task >= NTASK) break;
        const int stripe = task & (NSTRIPE - 1);   // consecutive tasks share a chunk
        const int chunk  = task >> 4;
        const int n0     = stripe * 64;
        const int b      = chunk * CHUNKB + wid;

        unsigned long long S[STEPS];
#pragma unroll
        for (int t = 0; t < STEPS; t++) S[t] = 0ull;

        for (int kh = 0; kh < 2; kh++) {
            __syncthreads();                       // walks of previous phase done
            for (int i = tid; i < 512 * 16; i += 1024) {
                int k = i >> 4, q = i & 15;
                *(float4*)(smem + k * 256 + q * 16) =
                    *(const float4*)&W2[(size_t)(kh * 512 + k) * H_N + n0 + q * 4];
            }
            __syncthreads();

#pragma unroll
            for (int th = 0; th < 2; th++) {
                const unsigned* L = g_klist[b][th][kh];
                const unsigned* D = g_gdesc[b][th][kh];
                const int gcnt = (int)g_gcnt[b][th][kh];
                int ptr = 0;
                uint4 kk = *(const uint4*)L;
                unsigned d = D[0];
                for (int i = 0; i < gcnt; i++) {
                    unsigned dn = D[i + 1];
                    const int end = (int)(d >> 5);
                    unsigned long long G0 = 0ull, G1 = 0ull;
                    for (; ptr < end; ptr += 4) {
                        uint4 nx = *(const uint4*)&L[ptr + 4];
                        unsigned long long v0, v1, v2, v3;
                        asm("ld.shared.b64 %0, [%1];" : "=l"(v0) : "r"(lbase + kk.x));
                        asm("ld.shared.b64 %0, [%1];" : "=l"(v1) : "r"(lbase + kk.y));
                        asm("ld.shared.b64 %0, [%1];" : "=l"(v2) : "r"(lbase + kk.z));
                        asm("ld.shared.b64 %0, [%1];" : "=l"(v3) : "r"(lbase + kk.w));
                        ADD2(G0, G0, v0);
                        ADD2(G1, G1, v1);
                        ADD2(G0, G0, v2);
                        ADD2(G1, G1, v3);
                        kk = nx;
                    }
                    unsigned long long G;
                    ADD2(G, G0, G1);
                    if (d & 1u)  ADD2(S[th * 5 + 0], S[th * 5 + 0], G);
                    if (d & 2u)  ADD2(S[th * 5 + 1], S[th * 5 + 1], G);
                    if (d & 4u)  ADD2(S[th * 5 + 2], S[th * 5 + 2], G);
                    if (d & 8u)  ADD2(S[th * 5 + 3], S[th * 5 + 3], G);
                    if (d & 16u) ADD2(S[th * 5 + 4], S[th * 5 + 4], G);
                    d = dn;
                }
            }
        }

        // LIF over all 10 steps; emit s2 spike codes (2 cols packed in one u32)
        {
            const float2 b2v = *(const float2*)&b2[n0 + lane * 2];
            float2 m2 = make_float2(0.f, 0.f);
            unsigned code = 0;
#pragma unroll
            for (int t = 0; t < STEPS; t++) {
                unsigned slo, shi;
                asm("mov.b64 {%0, %1}, %2;" : "=r"(slo), "=r"(shi) : "l"(S[t]));
                float cx = __uint_as_float(slo) + b2v.x;
                float cy = __uint_as_float(shi) + b2v.y;
                float rx = (m2.x > THR) ? THR : 0.f;
                float ry = (m2.y > THR) ? THR : 0.f;
                m2.x = BETA * m2.x + cx - rx;
                m2.y = BETA * m2.y + cy - ry;
                if (m2.x > THR) code |= 1u << t;
                if (m2.y > THR) code |= 1u << (16 + t);
            }
            *(unsigned*)&g_s2code[b][n0 + lane * 2] = code;
        }
    }
}

// ---------------- K5: s2 codes -> Wo subset-sums, output LIF, mean ----------------
__global__ __launch_bounds__(256) void k5_out(const float* __restrict__ Wo,
                                              const float* __restrict__ bo,
                                              float* __restrict__ out) {
    __shared__ float sWo[H_N];
    for (int i = threadIdx.x; i < H_N; i += 256) sWo[i] = Wo[i];
    __syncthreads();
    const int wid = threadIdx.x >> 5, lane = threadIdx.x & 31;
    const int b = blockIdx.x * 8 + wid;

    float S[STEPS];
#pragma unroll
    for (int t = 0; t < STEPS; t++) S[t] = 0.f;

    for (int j = 0; j < 32; j++) {
        unsigned code = g_s2code[b][j * 32 + lane];
        float w = sWo[j * 32 + lane];
#pragma unroll
        for (int t = 0; t < STEPS; t++)
            S[t] += ((code >> t) & 1u) ? w : 0.f;
    }
#pragma unroll
    for (int t = 0; t < STEPS; t++)
#pragma unroll
        for (int off = 16; off; off >>= 1)
            S[t] += __shfl_down_sync(0xFFFFFFFFu, S[t], off);

    if (lane == 0) {
        const float bo0 = bo[0];
        float mo = 0.f, acc = 0.f;
#pragma unroll
        for (int t = 0; t < STEPS; t++) {
            float tot = S[t] + bo0;
            float r = (mo > THR) ? THR : 0.f;
            mo = BETA * mo + tot - r;
            acc += mo;
        }
        out[b] = acc * (1.f / STEPS);
    }
}

// ---------------- launcher ----------------
extern "C" void kernel_launch(void* const* d_in, const int* in_sizes, int n_in,
                              void* d_out, int out_size) {
    const float* x  = (const float*)d_in[0];
    const float* W1 = (const float*)d_in[1];
    const float* b1 = (const float*)d_in[2];
    const float* W2 = (const float*)d_in[3];
    const float* b2 = (const float*)d_in[4];
    const float* Wo = (const float*)d_in[5];
    const float* bo = (const float*)d_in[6];
    float* out = (float*)d_out;

    cudaFuncSetAttribute(k3g, cudaFuncAttributeMaxDynamicSharedMemorySize, SMEMB);

    k1_gemm<<<dim3(H_N / 128, B_N / 128), 256>>>(x, W1, b1);
    k2b_sort<<<B_N / 8, 256>>>();
    k3g<<<148, 1024, SMEMB>>>(W2, b2);
    k5_out<<<B_N / 8, 256>>>(Wo, bo, out);
}

// round 14
// speedup vs baseline: 1.1695x; 1.1695x over previous
#include <cuda_runtime.h>
#include <cstdint>

#define B_N   65536
#define IN_N  512
#define H_N   1024
#define STEPS 10
#define BETA  0.9f
#define THR   1.0f

#define NSTRIPE 16                     // 1024 cols / 64
#define CHUNKB  32                     // b's per task (32 warps x 1)
#define NCHUNK  (B_N / CHUNKB)         // 2048
#define NTASK   (NSTRIPE * NCHUNK)     // 32768
#define LISTW   2080                   // worst-case 512 entries 4-aligned + margin

// smem layout for k3g
#define SM_W2    0                     // 512 rows x 256B = 131072
#define SM_DUMMY 131072                // 512B zero row (offset 131072 = dummy)
#define SM_MASK  131584                // 1024 x u16 group-mask LUT
#define SMEMB    (131584 + 2048)

#define ADD2(d, a, b) asm("add.rn.f32x2 %0, %1, %2;" : "=l"(d) : "l"(a), "l"(b))

// ---------------- static scratch ----------------
__device__ unsigned short g_code[B_N][H_N];                // layer-1 10-bit spike codes
__device__ unsigned       g_klist[B_N][2][LISTW];          // [b][khalf] offsets klocal*256
__device__ unsigned short g_gend[B_N][2][1024];            // cumulative group ends (per gid)
__device__ unsigned short g_s2code[B_N][H_N];              // layer-2 10-bit spike codes
__device__ unsigned       g_codebm[32];                    // presence bitmap of codes
__device__ unsigned short g_gidof[1024];                   // code -> gid
__device__ unsigned short g_maskof[1024];                  // gid  -> code (10-bit mask)
__device__ unsigned       g_ngids;
__device__ unsigned       g_ticket;

// ---------------- K1: cur1 GEMM + fused layer-1 LIF -> codes + presence bytes --------
__global__ __launch_bounds__(256) void k1_gemm(const float* __restrict__ X,
                                               const float* __restrict__ W1,
                                               const float* __restrict__ b1) {
    __shared__ float As[16][128];
    __shared__ float Bs[16][128];
    __shared__ unsigned char present[1024];
    const int tid = threadIdx.x;
    const int tx = tid & 15, ty = tid >> 4;
    const int m0 = blockIdx.y * 128;
    const int n0 = blockIdx.x * 128;
    *(unsigned*)&present[tid * 4] = 0u;

    float acc[8][8];
#pragma unroll
    for (int i = 0; i < 8; i++)
#pragma unroll
        for (int j = 0; j < 8; j++) acc[i][j] = 0.f;

    for (int kc = 0; kc < IN_N; kc += 16) {
        float4 av[2], bv[2];
#pragma unroll
        for (int l = 0; l < 2; l++) {
            int f = tid + l * 256;
            int row = f >> 2, kq = (f & 3) * 4;
            av[l] = *(const float4*)&X[(size_t)(m0 + row) * IN_N + kc + kq];
            int kr = f >> 5, c4 = (f & 31) * 4;
            bv[l] = *(const float4*)&W1[(size_t)(kc + kr) * H_N + n0 + c4];
        }
        __syncthreads();
#pragma unroll
        for (int l = 0; l < 2; l++) {
            int f = tid + l * 256;
            int row = f >> 2, kq = (f & 3) * 4;
            As[kq + 0][row] = av[l].x; As[kq + 1][row] = av[l].y;
            As[kq + 2][row] = av[l].z; As[kq + 3][row] = av[l].w;
            int kr = f >> 5, c4 = (f & 31) * 4;
            *(float4*)&Bs[kr][c4] = bv[l];
        }
        __syncthreads();
#pragma unroll
        for (int kk = 0; kk < 16; kk++) {
            float a[8], bb[8];
            *(float4*)&a[0]  = *(float4*)&As[kk][ty * 8];
            *(float4*)&a[4]  = *(float4*)&As[kk][ty * 8 + 4];
            *(float4*)&bb[0] = *(float4*)&Bs[kk][tx * 8];
            *(float4*)&bb[4] = *(float4*)&Bs[kk][tx * 8 + 4];
#pragma unroll
            for (int i = 0; i < 8; i++)
#pragma unroll
                for (int j = 0; j < 8; j++) acc[i][j] += a[i] * bb[j];
        }
    }

    float bias[8];
#pragma unroll
    for (int j = 0; j < 8; j++) bias[j] = b1[n0 + tx * 8 + j];

#pragma unroll
    for (int i = 0; i < 8; i++) {
        int row = m0 + ty * 8 + i;
        unsigned short codes[8];
#pragma unroll
        for (int j = 0; j < 8; j++) {
            float c = acc[i][j] + bias[j];
            float m = 0.f;
            unsigned code = 0;
#pragma unroll
            for (int t = 0; t < STEPS; t++) {
                float r = (m > THR) ? THR : 0.f;
                m = BETA * m + c - r;
                code |= (m > THR) ? (1u << t) : 0u;
            }
            codes[j] = (unsigned short)code;
            present[code] = 1;                      // racy identical stores: fine
        }
        *(uint4*)&g_code[row][n0 + tx * 8] = *(const uint4*)codes;
    }
    __syncthreads();
    if (tid < 32) {
        unsigned w = 0;
#pragma unroll
        for (int j = 0; j < 32; j++)
            if (present[tid * 32 + j]) w |= 1u << j;
        if (w) atomicOr(&g_codebm[tid], w);
    }
}

// ---------------- K2a: build code dictionary; reset ticket ----------------
__global__ void k2a_dict() {
    if (threadIdx.x == 0) {
        g_ticket = 0;
        int gid = 0;
        for (int c = 1; c < 1024; c++) {
            if ((g_codebm[c >> 5] >> (c & 31)) & 1u) {
                g_gidof[c] = (unsigned short)gid;
                g_maskof[gid] = (unsigned short)c;
                gid++;
            }
        }
        g_ngids = (unsigned)gid;
    }
}

// ---------------- K2b: per-(b,khalf) counting sort by gid (4-aligned groups) ----------
// warp per b; groups 4-aligned, padded with DUMMY (zero row). code 0 excluded.
__global__ __launch_bounds__(256) void k2b_sort() {
    __shared__ int hist[8][1024];
    const int wid  = threadIdx.x >> 5;
    const int lane = threadIdx.x & 31;
    const int b    = blockIdx.x * 8 + wid;
    const int ng   = (int)g_ngids;
    const unsigned short* codes = g_code[b];
    const unsigned ltmask = (1u << lane) - 1u;
    const unsigned DUMMY = 131072u;

    for (int kh = 0; kh < 2; kh++) {
        for (int i = lane; i < ng; i += 32) hist[wid][i] = 0;
        __syncwarp();
        // pass 1: counts (smem atomics; order-independent)
        for (int it = 0; it < 16; it++) {
            unsigned c = codes[kh * 512 + it * 32 + lane];
            if (c) atomicAdd(&hist[wid][g_gidof[c]], 1);
        }
        __syncwarp();
        // scan of 4-aligned padded counts -> ends (gmem) + start cursors (smem)
        int carry = 0;
        for (int base = 0; base < ng; base += 32) {
            int idx = base + lane;
            int cv = (idx < ng) ? hist[wid][idx] : 0;
            int pv = cv ? ((cv + 3) & ~3) : 0;
            int s = pv;
#pragma unroll
            for (int off = 1; off < 32; off <<= 1) {
                int n = __shfl_up_sync(0xFFFFFFFFu, s, off);
                if (lane >= off) s += n;
            }
            s += carry;
            if (idx < ng) {
                g_gend[b][kh][idx] = (unsigned short)s;
                hist[wid][idx] = s - pv;          // start cursor
            }
            carry = __shfl_sync(0xFFFFFFFFu, s, 31);
        }
        __syncwarp();
        // pass 2: deterministic scatter (byte offsets klocal*256)
        for (int it = 0; it < 16; it++) {
            unsigned c = codes[kh * 512 + it * 32 + lane];
            int gid = c ? (int)g_gidof[c] : -1;
            unsigned mm = __match_any_sync(0xFFFFFFFFu, gid);
            unsigned rank = __popc(mm & ltmask);
            int pos0 = (gid >= 0) ? hist[wid][gid] : 0;
            __syncwarp();
            if (gid >= 0) g_klist[b][kh][pos0 + rank] = (unsigned)(it * 32 + lane) * 256u;
            if (gid >= 0 && (__ffs(mm) - 1) == lane) hist[wid][gid] = pos0 + __popc(mm);
            __syncwarp();
        }
        // pad fill to 4-alignment (end = round-up of final cursor)
        for (int i = lane; i < ng; i += 32) {
            int cur = hist[wid][i], end = (cur + 3) & ~3;
            for (int p = cur; p < end; p++) g_klist[b][kh][p] = DUMMY;
        }
        __syncwarp();
    }
}

// ---------------- K3g: slot-scan group-sum GEMM + fused layer-2 LIF -> s2 codes ------
// Persistent CTAs (1024 thr = 32 warps). Warp owns ONE b, lane covers 2 cols.
// W2 staged per k-half; gid slots scanned in 32-blocks (lane-parallel ends + shfl).
// Accumulation in packed f32x2 (add.rn.f32x2), loads as plain u64 (LDS.64).
__global__ __launch_bounds__(1024, 1) void k3g(const float* __restrict__ W2,
                                               const float* __restrict__ b2) {
    extern __shared__ char smem[];
    __shared__ unsigned sTask;
    const int tid  = threadIdx.x;
    const int lane = tid & 31, wid = tid >> 5;
    const unsigned laneB = lane * 8;
    const int ng = (int)g_ngids;

    if (tid < 64) *(unsigned long long*)(smem + SM_DUMMY + tid * 8) = 0ull;
    { int i = tid; if (i < 1024) ((unsigned short*)(smem + SM_MASK))[i] = g_maskof[i]; }
    __syncthreads();

    for (;;) {
        if (tid == 0) sTask = atomicAdd(&g_ticket, 1u);
        __syncthreads();
        const unsigned task = sTask;
        __syncthreads();
        if (task >= NTASK) break;
        const int stripe = task & (NSTRIPE - 1);   // consecutive tasks share a chunk
        const int chunk  = task >> 4;
        const int n0     = stripe * 64;
        const int b      = chunk * CHUNKB + wid;

        unsigned long long S[STEPS];
#pragma unroll
        for (int t = 0; t < STEPS; t++) S[t] = 0ull;

        for (int kh = 0; kh < 2; kh++) {
            __syncthreads();                       // walks of previous phase done
            for (int i = tid; i < 512 * 16; i += 1024) {
                int k = i >> 4, q = i & 15;
                *(float4*)(smem + k * 256 + q * 16) =
                    *(const float4*)&W2[(size_t)(kh * 512 + k) * H_N + n0 + q * 4];
            }
            __syncthreads();

            const unsigned short* ends = g_gend[b][kh];
            const unsigned* L = g_klist[b][kh];
            int ptr = 0;
            uint4 kk = *(const uint4*)L;
            for (int gb = 0; gb < ng; gb += 32) {
                int e = 0;
                if (gb + lane < ng) e = (int)ends[gb + lane];
                const int lim = (ng - gb < 32) ? (ng - gb) : 32;
                for (int g2 = 0; g2 < lim; g2++) {
                    int end = __shfl_sync(0xFFFFFFFFu, e, g2);
                    if (end <= ptr) continue;
                    unsigned long long G0 = 0ull, G1 = 0ull;
                    for (; ptr < end; ptr += 4) {
                        uint4 nx = *(const uint4*)&L[ptr + 4];
                        unsigned long long v0 = *(const unsigned long long*)(smem + kk.x + laneB);
                        unsigned long long v1 = *(const unsigned long long*)(smem + kk.y + laneB);
                        unsigned long long v2 = *(const unsigned long long*)(smem + kk.z + laneB);
                        unsigned long long v3 = *(const unsigned long long*)(smem + kk.w + laneB);
                        ADD2(G0, G0, v0);
                        ADD2(G1, G1, v1);
                        ADD2(G0, G0, v2);
                        ADD2(G1, G1, v3);
                        kk = nx;
                    }
                    unsigned long long G;
                    ADD2(G, G0, G1);
                    const unsigned mask = ((const unsigned short*)(smem + SM_MASK))[gb + g2];
                    if (mask & 1u)   ADD2(S[0], S[0], G);
                    if (mask & 2u)   ADD2(S[1], S[1], G);
                    if (mask & 4u)   ADD2(S[2], S[2], G);
                    if (mask & 8u)   ADD2(S[3], S[3], G);
                    if (mask & 16u)  ADD2(S[4], S[4], G);
                    if (mask & 32u)  ADD2(S[5], S[5], G);
                    if (mask & 64u)  ADD2(S[6], S[6], G);
                    if (mask & 128u) ADD2(S[7], S[7], G);
                    if (mask & 256u) ADD2(S[8], S[8], G);
                    if (mask & 512u) ADD2(S[9], S[9], G);
                }
            }
        }

        // LIF over all 10 steps; emit s2 spike codes (2 cols packed in one u32)
        {
            const float2 b2v = *(const float2*)&b2[n0 + lane * 2];
            float2 m2 = make_float2(0.f, 0.f);
            unsigned code = 0;
#pragma unroll
            for (int t = 0; t < STEPS; t++) {
                unsigned slo, shi;
                asm("mov.b64 {%0, %1}, %2;" : "=r"(slo), "=r"(shi) : "l"(S[t]));
                float cx = __uint_as_float(slo) + b2v.x;
                float cy = __uint_as_float(shi) + b2v.y;
                float rx = (m2.x > THR) ? THR : 0.f;
                float ry = (m2.y > THR) ? THR : 0.f;
                m2.x = BETA * m2.x + cx - rx;
                m2.y = BETA * m2.y + cy - ry;
                if (m2.x > THR) code |= 1u << t;
                if (m2.y > THR) code |= 1u << (16 + t);
            }
            *(unsigned*)&g_s2code[b][n0 + lane * 2] = code;
        }
    }
}

// ---------------- K5: s2 codes -> Wo subset-sums, output LIF, mean ----------------
__global__ __launch_bounds__(256) void k5_out(const float* __restrict__ Wo,
                                              const float* __restrict__ bo,
                                              float* __restrict__ out) {
    __shared__ float sWo[H_N];
    for (int i = threadIdx.x; i < H_N; i += 256) sWo[i] = Wo[i];
    __syncthreads();
    const int wid = threadIdx.x >> 5, lane = threadIdx.x & 31;
    const int b = blockIdx.x * 8 + wid;

    float S[STEPS];
#pragma unroll
    for (int t = 0; t < STEPS; t++) S[t] = 0.f;

    for (int j = 0; j < 32; j++) {
        unsigned code = g_s2code[b][j * 32 + lane];
        float w = sWo[j * 32 + lane];
#pragma unroll
        for (int t = 0; t < STEPS; t++)
            S[t] += ((code >> t) & 1u) ? w : 0.f;
    }
#pragma unroll
    for (int t = 0; t < STEPS; t++)
#pragma unroll
        for (int off = 16; off; off >>= 1)
            S[t] += __shfl_down_sync(0xFFFFFFFFu, S[t], off);

    if (lane == 0) {
        const float bo0 = bo[0];
        float mo = 0.f, acc = 0.f;
#pragma unroll
        for (int t = 0; t < STEPS; t++) {
            float tot = S[t] + bo0;
            float r = (mo > THR) ? THR : 0.f;
            mo = BETA * mo + tot - r;
            acc += mo;
        }
        out[b] = acc * (1.f / STEPS);
    }
}

// ---------------- launcher ----------------
extern "C" void kernel_launch(void* const* d_in, const int* in_sizes, int n_in,
                              void* d_out, int out_size) {
    const float* x  = (const float*)d_in[0];
    const float* W1 = (const float*)d_in[1];
    const float* b1 = (const float*)d_in[2];
    const float* W2 = (const float*)d_in[3];
    const float* b2 = (const float*)d_in[4];
    const float* Wo = (const float*)d_in[5];
    const float* bo = (const float*)d_in[6];
    float* out = (float*)d_out;

    cudaFuncSetAttribute(k3g, cudaFuncAttributeMaxDynamicSharedMemorySize, SMEMB);

    k1_gemm<<<dim3(H_N / 128, B_N / 128), 256>>>(x, W1, b1);
    k2a_dict<<<1, 32>>>();
    k2b_sort<<<B_N / 8, 256>>>();
    k3g<<<148, 1024, SMEMB>>>(W2, b2);
    k5_out<<<B_N / 8, 256>>>(Wo, bo, out);
}